// round 10
// baseline (speedup 1.0000x reference)
#include <cuda_runtime.h>
#include <cuda_fp16.h>
#include <cstdint>

#define NB 16
#define NC 512
#define NN 1024
#define NH 8
#define ND 64

// ---------------- scratch (device globals; allocation-free) ----------------
__device__ __align__(16) __half g_qh[(size_t)NB*NC*NN];
__device__ __align__(16) __half g_kh[(size_t)NB*NC*NN];
__device__ __align__(16) __half g_vh[(size_t)NB*NC*NN];
__device__ __align__(16) __half g_xh[(size_t)NB*NC*NN];
__device__ __align__(16) __half g_wh[(size_t)3*NC*NC];
__device__ __align__(16) __half g_ph[(size_t)NC*NN];

// ---------------- helpers ----------------
__device__ __forceinline__ void cp16(uint32_t dst, const void* src){
    asm volatile("cp.async.cg.shared.global [%0], [%1], 16;" :: "r"(dst), "l"(src));
}
__device__ __forceinline__ void cp_commit(){ asm volatile("cp.async.commit_group;"); }
template<int N> __device__ __forceinline__ void cp_wait(){
    asm volatile("cp.async.wait_group %0;" :: "n"(N));
}
__device__ __forceinline__ void ldsm4(uint32_t r[4], uint32_t a){
    asm volatile("ldmatrix.sync.aligned.m8n8.x4.shared.b16 {%0,%1,%2,%3},[%4];"
        : "=r"(r[0]),"=r"(r[1]),"=r"(r[2]),"=r"(r[3]) : "r"(a));
}
__device__ __forceinline__ void ldsm4t(uint32_t r[4], uint32_t a){
    asm volatile("ldmatrix.sync.aligned.m8n8.x4.trans.shared.b16 {%0,%1,%2,%3},[%4];"
        : "=r"(r[0]),"=r"(r[1]),"=r"(r[2]),"=r"(r[3]) : "r"(a));
}
__device__ __forceinline__ void ldsm2t(uint32_t r[2], uint32_t a){
    asm volatile("ldmatrix.sync.aligned.m8n8.x2.trans.shared.b16 {%0,%1},[%2];"
        : "=r"(r[0]),"=r"(r[1]) : "r"(a));
}
__device__ __forceinline__ void ldsm2(uint32_t r[2], uint32_t a){
    asm volatile("ldmatrix.sync.aligned.m8n8.x2.shared.b16 {%0,%1},[%2];"
        : "=r"(r[0]),"=r"(r[1]) : "r"(a));
}
__device__ __forceinline__ void mma_f16(float* c, const uint32_t* a, const uint32_t* b){
    asm volatile("mma.sync.aligned.m16n8k16.row.col.f32.f16.f16.f32 "
        "{%0,%1,%2,%3},{%4,%5,%6,%7},{%8,%9},{%0,%1,%2,%3};"
        : "+f"(c[0]),"+f"(c[1]),"+f"(c[2]),"+f"(c[3])
        : "r"(a[0]),"r"(a[1]),"r"(a[2]),"r"(a[3]),"r"(b[0]),"r"(b[1]));
}
__device__ __forceinline__ uint32_t packh2(float x, float y){
    __half2 t = __floats2half2_rn(x, y);
    return *reinterpret_cast<uint32_t*>(&t);
}

// ---------------- convert fp32 -> fp16 ----------------
__global__ void cvt_kernel(const float* __restrict__ s, int sel, size_t off, int n4){
    int i = blockIdx.x * blockDim.x + threadIdx.x;
    if (i >= n4) return;
    __half* dst = sel ? (g_wh + off) : g_xh;
    float4 v = reinterpret_cast<const float4*>(s)[i];
    __half2* d2 = reinterpret_cast<__half2*>(dst + (size_t)4*i);
    d2[0] = __floats2half2_rn(v.x, v.y);
    d2[1] = __floats2half2_rn(v.z, v.w);
}

__global__ void pos_cvt_kernel(const float* __restrict__ rel_h,
                               const float* __restrict__ rel_w){
    int idx = blockIdx.x * blockDim.x + threadIdx.x;
    if (idx >= NC*NN) return;
    int hd = idx >> 10, n = idx & 1023;
    g_ph[idx] = __float2half(rel_h[hd*32 + (n & 31)] + rel_w[hd*32 + (n >> 5)]);
}

// ---------------- QKV GEMM: out[b][o][n] = sum_c W[o][c] x[b][c][n] + bias ----------------
// 128(o) x 128(n) tile, k-step 32, fp16 single-term, cp.async double buffer. 32KB smem.
__global__ __launch_bounds__(256) void qkv_mma_kernel(
    const float* __restrict__ bq, const float* __restrict__ bk,
    const float* __restrict__ bv)
{
    extern __shared__ uint4 smemraw[];
    const uint32_t sbase = (uint32_t)__cvta_generic_to_shared(smemraw);
    const int tid = threadIdx.x, lane = tid & 31, warp = tid >> 5;
    const int wm = warp >> 2, wn = warp & 3;
    const int which = blockIdx.z % 3;
    const int b = blockIdx.z / 3;
    const int oT = blockIdx.y * 128, nT = blockIdx.x * 128;

    const __half* Wh = g_wh + (size_t)which*NC*NC;
    const __half* Xh = g_xh + (size_t)b*NC*NN;
    const float* bias = (which==0) ? bq : (which==1) ? bk : bv;
    __half* Oh = (which==0) ? g_qh : (which==1) ? g_kh : g_vh;

    auto aAddr = [&](int buf,int row,int u)->uint32_t{
        return sbase + (uint32_t)(buf*512 + row*4 + (u ^ ((row>>1)&3)))*16u; };
    auto bAddr = [&](int buf,int row,int u)->uint32_t{
        return sbase + (uint32_t)(1024 + buf*512 + row*16 + (u ^ (row&7)))*16u; };

    auto issue = [&](int ct, int buf){
        #pragma unroll
        for (int s = 0; s < 2; s++){
            int idx = tid + (s<<8);
            int row = idx >> 2, u = idx & 3;
            cp16(aAddr(buf,row,u), Wh + (size_t)(oT+row)*NC + ct + u*8);
        }
        #pragma unroll
        for (int s = 0; s < 2; s++){
            int idx = tid + (s<<8);
            int row = idx >> 4, u = idx & 15;
            cp16(bAddr(buf,row,u), Xh + (size_t)(ct+row)*NN + nT + u*8);
        }
    };

    float C[4][4][4];
    #pragma unroll
    for (int a=0;a<4;a++)
        #pragma unroll
        for (int bb=0;bb<4;bb++)
            #pragma unroll
            for (int c=0;c<4;c++) C[a][bb][c]=0.f;

    issue(0, 0); cp_commit();
    for (int it = 0; it < 16; it++){
        if (it < 15){ issue((it+1)*32, (it+1)&1); cp_commit(); cp_wait<1>(); }
        else        { cp_wait<0>(); }
        __syncthreads();
        int buf = it & 1;
        #pragma unroll
        for (int k16 = 0; k16 < 2; k16++){
            int kk = k16 << 4;
            uint32_t ah[4][4], bh[4][2];
            #pragma unroll
            for (int mi = 0; mi < 4; mi++){
                int row = wm*64 + mi*16 + (lane & 15);
                int kg  = (kk >> 3) + (lane >> 4);
                ldsm4(ah[mi], aAddr(buf,row,kg));
            }
            #pragma unroll
            for (int ni = 0; ni < 4; ni++){
                int row = kk + (lane & 15);
                int u = wn*4 + ni;
                ldsm2t(bh[ni], bAddr(buf,row,u));
            }
            #pragma unroll
            for (int mi = 0; mi < 4; mi++)
                #pragma unroll
                for (int ni = 0; ni < 4; ni++)
                    mma_f16(C[mi][ni], ah[mi], bh[ni]);
        }
        __syncthreads();
    }
    #pragma unroll
    for (int mi = 0; mi < 4; mi++){
        int r0 = oT + wm*64 + mi*16 + (lane >> 2);
        float bi0 = bias[r0], bi1 = bias[r0 + 8];
        #pragma unroll
        for (int ni = 0; ni < 4; ni++){
            int c0 = nT + wn*32 + ni*8 + (lane & 3)*2;
            size_t o0 = ((size_t)b*NC + r0)*NN + c0;
            *reinterpret_cast<__half2*>(Oh + o0) =
                __floats2half2_rn(C[mi][ni][0]+bi0, C[mi][ni][1]+bi0);
            *reinterpret_cast<__half2*>(Oh + o0 + (size_t)8*NN) =
                __floats2half2_rn(C[mi][ni][2]+bi1, C[mi][ni][3]+bi1);
        }
    }
}

// ---------------- attention: flash-style + online max, fp16, BM=128, BN=64 ----------------
// smem 16B-units: Q' [0,2048): r*16+(u^(r&7)); K' 2048+buf*1024+r*8+(u^(r&7));
// V 4096+buf*512+r*8+(u^(r&7)).  Total 5120 units = 80KB -> 2 CTAs/SM.
__global__ __launch_bounds__(256, 2) void attn_mma_kernel(const float* __restrict__ x,
                                                          float* __restrict__ out)
{
    extern __shared__ uint4 smemraw[];
    const uint32_t sbase = (uint32_t)__cvta_generic_to_shared(smemraw);
    float* smf = reinterpret_cast<float*>(smemraw);
    const int tid = threadIdx.x, lane = tid & 31, warp = tid >> 5;
    const int wm = warp >> 1, wn = warp & 1;
    const int b = blockIdx.z, h = blockIdx.y;
    const int i0 = blockIdx.x * 128;
    const size_t qoff = ((size_t)b*NC + h*ND)*NN;

    auto loadQ = [&](){
        #pragma unroll
        for (int s = 0; s < 8; s++){
            int idx = tid + s*256;
            int r = idx >> 4, u = idx & 15;
            const __half* src = (r < 64)
                ? g_qh + qoff + (size_t)r*NN + i0 + u*8
                : g_ph + ((size_t)h*ND + (r-64))*NN + i0 + u*8;
            cp16(sbase + (uint32_t)(r*16 + (u ^ (r&7)))*16u, src);
        }
    };
    auto loadKV = [&](int jt, int buf){
        int j0 = jt * 64;
        #pragma unroll
        for (int s = 0; s < 4; s++){
            int idx = tid + s*256;
            int r = idx >> 3, u = idx & 7;
            const __half* src = (r < 64)
                ? g_kh + qoff + (size_t)r*NN + j0 + u*8
                : g_qh + qoff + (size_t)(r-64)*NN + j0 + u*8;
            cp16(sbase + (uint32_t)(2048 + buf*1024 + r*8 + (u ^ (r&7)))*16u, src);
        }
        #pragma unroll
        for (int s = 0; s < 2; s++){
            int idx = tid + s*256;
            int r = idx >> 3, u = idx & 7;
            const __half* src = g_vh + qoff + (size_t)r*NN + j0 + u*8;
            cp16(sbase + (uint32_t)(4096 + buf*512 + r*8 + (u ^ (r&7)))*16u, src);
        }
    };

    float Oc[2][8][4];
    #pragma unroll
    for (int a=0;a<2;a++)
        #pragma unroll
        for (int bb=0;bb<8;bb++)
            #pragma unroll
            for (int c=0;c<4;c++) Oc[a][bb][c]=0.f;
    float rs[2][2] = {{0.f,0.f},{0.f,0.f}};
    float mr[2][2] = {{-1e30f,-1e30f},{-1e30f,-1e30f}};

    loadQ(); loadKV(0, 0); cp_commit();

    for (int jt = 0; jt < 16; jt++){
        if (jt < 15){ loadKV(jt+1, (jt+1)&1); cp_commit(); cp_wait<1>(); }
        else        { cp_wait<0>(); }
        __syncthreads();
        int buf = jt & 1;

        // ---- S = Q'^T K' (k=128, 8 k16 steps, fp16 single-term) ----
        float S[2][4][4];
        #pragma unroll
        for (int a=0;a<2;a++)
            #pragma unroll
            for (int bb=0;bb<4;bb++)
                #pragma unroll
                for (int c=0;c<4;c++) S[a][bb][c]=0.f;

        #pragma unroll
        for (int k16 = 0; k16 < 8; k16++){
            uint32_t aH[2][4], bH[4][2];
            int arow = k16*16 + (lane & 7) + ((lane >> 4) << 3);
            #pragma unroll
            for (int mi = 0; mi < 2; mi++){
                int au = wm*4 + mi*2 + ((lane >> 3) & 1);
                ldsm4t(aH[mi], sbase + (uint32_t)(arow*16 + (au ^ (arow&7)))*16u);
            }
            int brow = k16*16 + (lane & 15);
            #pragma unroll
            for (int ni = 0; ni < 4; ni++){
                int bu = wn*4 + ni;
                ldsm2t(bH[ni], sbase + (uint32_t)(2048 + buf*1024 + brow*8 + (bu ^ (brow&7)))*16u);
            }
            #pragma unroll
            for (int mi = 0; mi < 2; mi++)
                #pragma unroll
                for (int ni = 0; ni < 4; ni++)
                    mma_f16(S[mi][ni], aH[mi], bH[ni]);
        }

        // ---- online softmax (per-warp running max over its j-half) ----
        #pragma unroll
        for (int mi = 0; mi < 2; mi++){
            float t0 = -1e30f, t1 = -1e30f;
            #pragma unroll
            for (int ni = 0; ni < 4; ni++){
                t0 = fmaxf(t0, fmaxf(S[mi][ni][0], S[mi][ni][1]));
                t1 = fmaxf(t1, fmaxf(S[mi][ni][2], S[mi][ni][3]));
            }
            #pragma unroll
            for (int off = 1; off < 4; off <<= 1){
                t0 = fmaxf(t0, __shfl_xor_sync(0xffffffffu, t0, off));
                t1 = fmaxf(t1, __shfl_xor_sync(0xffffffffu, t1, off));
            }
            float nm0 = fmaxf(mr[mi][0], t0), nm1 = fmaxf(mr[mi][1], t1);
            float sc0 = __expf(mr[mi][0] - nm0), sc1 = __expf(mr[mi][1] - nm1);
            mr[mi][0] = nm0; mr[mi][1] = nm1;
            float ps0 = 0.f, ps1 = 0.f;
            #pragma unroll
            for (int ni = 0; ni < 4; ni++){
                S[mi][ni][0] = __expf(S[mi][ni][0] - nm0);
                S[mi][ni][1] = __expf(S[mi][ni][1] - nm0);
                S[mi][ni][2] = __expf(S[mi][ni][2] - nm1);
                S[mi][ni][3] = __expf(S[mi][ni][3] - nm1);
                ps0 += S[mi][ni][0] + S[mi][ni][1];
                ps1 += S[mi][ni][2] + S[mi][ni][3];
            }
            rs[mi][0] = rs[mi][0]*sc0 + ps0;
            rs[mi][1] = rs[mi][1]*sc1 + ps1;
            #pragma unroll
            for (int nd = 0; nd < 8; nd++){
                Oc[mi][nd][0] *= sc0; Oc[mi][nd][1] *= sc0;
                Oc[mi][nd][2] *= sc1; Oc[mi][nd][3] *= sc1;
            }
        }

        // ---- O += P V^T (P in regs as fp16 A-fragments; V from smem) ----
        #pragma unroll
        for (int kt = 0; kt < 2; kt++){
            uint32_t pF[2][4];
            #pragma unroll
            for (int mi = 0; mi < 2; mi++){
                pF[mi][0] = packh2(S[mi][2*kt  ][0], S[mi][2*kt  ][1]);
                pF[mi][1] = packh2(S[mi][2*kt  ][2], S[mi][2*kt  ][3]);
                pF[mi][2] = packh2(S[mi][2*kt+1][0], S[mi][2*kt+1][1]);
                pF[mi][3] = packh2(S[mi][2*kt+1][2], S[mi][2*kt+1][3]);
            }
            #pragma unroll
            for (int nd = 0; nd < 8; nd++){
                int vrow = nd*8 + (lane & 7);
                int vu = wn*4 + kt*2 + ((lane >> 3) & 1);
                uint32_t vF[2];
                ldsm2(vF, sbase + (uint32_t)(4096 + buf*512 + vrow*8 + (vu ^ (vrow&7)))*16u);
                #pragma unroll
                for (int mi = 0; mi < 2; mi++)
                    mma_f16(Oc[mi][nd], pF[mi], vF);
            }
        }
        __syncthreads();
    }

    // ---- cross-warp combine (max reconciliation), normalize, +x, store ----
    float* Os = smf;                   // [128 i][65] fp32 (tiles dead now)
    float* rsum_s = smf + 128*65;      // [128]
    float* mmax_s = rsum_s + 128;      // [128]
    #pragma unroll
    for (int off = 1; off < 4; off <<= 1)
        #pragma unroll
        for (int mi = 0; mi < 2; mi++){
            rs[mi][0] += __shfl_xor_sync(0xffffffffu, rs[mi][0], off);
            rs[mi][1] += __shfl_xor_sync(0xffffffffu, rs[mi][1], off);
        }
    if (wn == 0){
        #pragma unroll
        for (int mi = 0; mi < 2; mi++){
            int ib = wm*32 + mi*16 + (lane >> 2);
            #pragma unroll
            for (int nd = 0; nd < 8; nd++){
                int dd = nd*8 + (lane & 3)*2;
                Os[ib*65 + dd]       = Oc[mi][nd][0];
                Os[ib*65 + dd + 1]   = Oc[mi][nd][1];
                Os[(ib+8)*65 + dd]   = Oc[mi][nd][2];
                Os[(ib+8)*65 + dd+1] = Oc[mi][nd][3];
            }
            if ((lane & 3) == 0){
                rsum_s[ib]   = rs[mi][0]; rsum_s[ib+8] = rs[mi][1];
                mmax_s[ib]   = mr[mi][0]; mmax_s[ib+8] = mr[mi][1];
            }
        }
    }
    __syncthreads();
    if (wn == 1){
        #pragma unroll
        for (int mi = 0; mi < 2; mi++){
            int ib = wm*32 + mi*16 + (lane >> 2);
            float m0a = mmax_s[ib], m0b = mmax_s[ib+8];
            float Ma = fmaxf(m0a, mr[mi][0]), Mb = fmaxf(m0b, mr[mi][1]);
            float s0a = __expf(m0a - Ma), s1a = __expf(mr[mi][0] - Ma);
            float s0b = __expf(m0b - Mb), s1b = __expf(mr[mi][1] - Mb);
            #pragma unroll
            for (int nd = 0; nd < 8; nd++){
                int dd = nd*8 + (lane & 3)*2;
                Os[ib*65 + dd]       = Os[ib*65 + dd]      *s0a + Oc[mi][nd][0]*s1a;
                Os[ib*65 + dd + 1]   = Os[ib*65 + dd + 1]  *s0a + Oc[mi][nd][1]*s1a;
                Os[(ib+8)*65 + dd]   = Os[(ib+8)*65 + dd]  *s0b + Oc[mi][nd][2]*s1b;
                Os[(ib+8)*65 + dd+1] = Os[(ib+8)*65 + dd+1]*s0b + Oc[mi][nd][3]*s1b;
            }
            if ((lane & 3) == 0){
                rsum_s[ib]   = rsum_s[ib]  *s0a + rs[mi][0]*s1a;
                rsum_s[ib+8] = rsum_s[ib+8]*s0b + rs[mi][1]*s1b;
            }
        }
    }
    __syncthreads();
    if (tid < 128) rsum_s[tid] = 1.0f / rsum_s[tid];
    __syncthreads();

    const float* xb = x + qoff;
    float* ob = out + qoff;
    #pragma unroll
    for (int s = 0; s < 32; s++){
        int idx = tid + s*256;
        int dd = idx >> 7, iL = idx & 127;
        ob[(size_t)dd*NN + i0 + iL] =
            Os[iL*65 + dd] * rsum_s[iL] + xb[(size_t)dd*NN + i0 + iL];
    }
}

extern "C" void kernel_launch(void* const* d_in, const int* in_sizes, int n_in,
                              void* d_out, int out_size) {
    (void)in_sizes; (void)n_in; (void)out_size;
    const float* x     = (const float*)d_in[0];
    const float* Wq    = (const float*)d_in[1];
    const float* bq    = (const float*)d_in[2];
    const float* Wk    = (const float*)d_in[3];
    const float* bk    = (const float*)d_in[4];
    const float* Wv    = (const float*)d_in[5];
    const float* bv    = (const float*)d_in[6];
    const float* rel_h = (const float*)d_in[7];
    const float* rel_w = (const float*)d_in[8];
    // d_in[9]/d_in[10] (reg_qk/reg_v) are provably dead: the reg group is sliced
    // away by out[:, :head] and softmax/PV are group-independent.
    float* out = (float*)d_out;

    cudaFuncSetAttribute(qkv_mma_kernel,
        cudaFuncAttributeMaxDynamicSharedMemorySize, 32768);
    cudaFuncSetAttribute(attn_mma_kernel,
        cudaFuncAttributeMaxDynamicSharedMemorySize, 81920);

    cvt_kernel<<<8192, 256>>>(x,  0, 0, 2097152);
    cvt_kernel<<<256, 256>>>(Wq, 1, 0, 65536);
    cvt_kernel<<<256, 256>>>(Wk, 1, (size_t)NC*NC, 65536);
    cvt_kernel<<<256, 256>>>(Wv, 1, (size_t)2*NC*NC, 65536);
    pos_cvt_kernel<<<2048, 256>>>(rel_h, rel_w);
    qkv_mma_kernel<<<dim3(NN/128, NC/128, 3*NB), 256, 32768>>>(bq, bk, bv);
    attn_mma_kernel<<<dim3(NN/128, NH, NB), 256, 81920>>>(x, out);
}

// round 14
// speedup vs baseline: 1.0620x; 1.0620x over previous
#include <cuda_runtime.h>
#include <cuda_fp16.h>
#include <cstdint>

#define NB 16
#define NC 512
#define NN 1024
#define NH 8
#define ND 64
#define LOG2E 1.4426950408889634f

// ---------------- scratch (device globals; allocation-free) ----------------
__device__ __align__(16) __half g_qh[(size_t)NB*NC*NN];
__device__ __align__(16) __half g_kh[(size_t)NB*NC*NN];   // scaled by log2e
__device__ __align__(16) __half g_vh[(size_t)NB*NC*NN];
__device__ __align__(16) __half g_xh[(size_t)NB*NC*NN];
__device__ __align__(16) __half g_wh[(size_t)3*NC*NC];    // Wk segment scaled by log2e
__device__ __align__(16) __half g_ph[(size_t)NC*NN];      // scaled by log2e

// ---------------- helpers ----------------
__device__ __forceinline__ void cp16(uint32_t dst, const void* src){
    asm volatile("cp.async.cg.shared.global [%0], [%1], 16;" :: "r"(dst), "l"(src));
}
__device__ __forceinline__ void cp_commit(){ asm volatile("cp.async.commit_group;"); }
template<int N> __device__ __forceinline__ void cp_wait(){
    asm volatile("cp.async.wait_group %0;" :: "n"(N));
}
__device__ __forceinline__ void ldsm4(uint32_t r[4], uint32_t a){
    asm volatile("ldmatrix.sync.aligned.m8n8.x4.shared.b16 {%0,%1,%2,%3},[%4];"
        : "=r"(r[0]),"=r"(r[1]),"=r"(r[2]),"=r"(r[3]) : "r"(a));
}
__device__ __forceinline__ void ldsm4t(uint32_t r[4], uint32_t a){
    asm volatile("ldmatrix.sync.aligned.m8n8.x4.trans.shared.b16 {%0,%1,%2,%3},[%4];"
        : "=r"(r[0]),"=r"(r[1]),"=r"(r[2]),"=r"(r[3]) : "r"(a));
}
__device__ __forceinline__ void ldsm2t(uint32_t r[2], uint32_t a){
    asm volatile("ldmatrix.sync.aligned.m8n8.x2.trans.shared.b16 {%0,%1},[%2];"
        : "=r"(r[0]),"=r"(r[1]) : "r"(a));
}
__device__ __forceinline__ void ldsm2(uint32_t r[2], uint32_t a){
    asm volatile("ldmatrix.sync.aligned.m8n8.x2.shared.b16 {%0,%1},[%2];"
        : "=r"(r[0]),"=r"(r[1]) : "r"(a));
}
__device__ __forceinline__ void mma_f16(float* c, const uint32_t* a, const uint32_t* b){
    asm volatile("mma.sync.aligned.m16n8k16.row.col.f32.f16.f16.f32 "
        "{%0,%1,%2,%3},{%4,%5,%6,%7},{%8,%9},{%0,%1,%2,%3};"
        : "+f"(c[0]),"+f"(c[1]),"+f"(c[2]),"+f"(c[3])
        : "r"(a[0]),"r"(a[1]),"r"(a[2]),"r"(a[3]),"r"(b[0]),"r"(b[1]));
}
__device__ __forceinline__ uint32_t packh2(float x, float y){
    __half2 t = __floats2half2_rn(x, y);
    return *reinterpret_cast<uint32_t*>(&t);
}
__device__ __forceinline__ float ex2f(float x){
    float y; asm("ex2.approx.ftz.f32 %0,%1;" : "=f"(y) : "f"(x)); return y;
}

// ---------------- fused convert fp32 -> fp16 (x + Wq + Wk*log2e + Wv) ----------------
#define X4 2097152
#define W4 65536
__global__ void cvt_all_kernel(const float* __restrict__ x,
                               const float* __restrict__ Wq,
                               const float* __restrict__ Wk,
                               const float* __restrict__ Wv){
    int i = blockIdx.x * blockDim.x + threadIdx.x;
    const float* src; __half* dst; float sc = 1.f; int li;
    if (i < X4){ src = x; dst = g_xh; li = i; }
    else {
        int j = i - X4;
        int seg = j / W4; li = j - seg*W4;
        src = (seg==0) ? Wq : (seg==1) ? Wk : Wv;
        dst = g_wh + (size_t)seg*W4*4;
        if (seg == 1) sc = LOG2E;
    }
    float4 v = reinterpret_cast<const float4*>(src)[li];
    __half2* d2 = reinterpret_cast<__half2*>(dst + (size_t)4*li);
    d2[0] = __floats2half2_rn(v.x*sc, v.y*sc);
    d2[1] = __floats2half2_rn(v.z*sc, v.w*sc);
}

__global__ void pos_cvt_kernel(const float* __restrict__ rel_h,
                               const float* __restrict__ rel_w){
    int idx = blockIdx.x * blockDim.x + threadIdx.x;
    if (idx >= NC*NN) return;
    int hd = idx >> 10, n = idx & 1023;
    g_ph[idx] = __float2half((rel_h[hd*32 + (n & 31)] + rel_w[hd*32 + (n >> 5)]) * LOG2E);
}

// ---------------- QKV GEMM: out[b][o][n] = sum_c W[o][c] x[b][c][n] + bias ----------------
__global__ __launch_bounds__(256) void qkv_mma_kernel(
    const float* __restrict__ bq, const float* __restrict__ bk,
    const float* __restrict__ bv)
{
    extern __shared__ uint4 smemraw[];
    const uint32_t sbase = (uint32_t)__cvta_generic_to_shared(smemraw);
    const int tid = threadIdx.x, lane = tid & 31, warp = tid >> 5;
    const int wm = warp >> 2, wn = warp & 3;
    const int which = blockIdx.z % 3;
    const int b = blockIdx.z / 3;
    const int oT = blockIdx.y * 128, nT = blockIdx.x * 128;

    const __half* Wh = g_wh + (size_t)which*NC*NC;
    const __half* Xh = g_xh + (size_t)b*NC*NN;
    const float* bias = (which==0) ? bq : (which==1) ? bk : bv;
    __half* Oh = (which==0) ? g_qh : (which==1) ? g_kh : g_vh;
    const float bsc = (which==1) ? LOG2E : 1.f;

    auto aAddr = [&](int buf,int row,int u)->uint32_t{
        return sbase + (uint32_t)(buf*512 + row*4 + (u ^ ((row>>1)&3)))*16u; };
    auto bAddr = [&](int buf,int row,int u)->uint32_t{
        return sbase + (uint32_t)(1024 + buf*512 + row*16 + (u ^ (row&7)))*16u; };

    auto issue = [&](int ct, int buf){
        #pragma unroll
        for (int s = 0; s < 2; s++){
            int idx = tid + (s<<8); int row = idx >> 2, u = idx & 3;
            cp16(aAddr(buf,row,u), Wh + (size_t)(oT+row)*NC + ct + u*8);
        }
        #pragma unroll
        for (int s = 0; s < 2; s++){
            int idx = tid + (s<<8); int row = idx >> 4, u = idx & 15;
            cp16(bAddr(buf,row,u), Xh + (size_t)(ct+row)*NN + nT + u*8);
        }
    };

    float C[4][4][4];
    #pragma unroll
    for (int a=0;a<4;a++)
        #pragma unroll
        for (int bb=0;bb<4;bb++)
            #pragma unroll
            for (int c=0;c<4;c++) C[a][bb][c]=0.f;

    issue(0, 0); cp_commit();
    for (int it = 0; it < 16; it++){
        if (it < 15){ issue((it+1)*32, (it+1)&1); cp_commit(); cp_wait<1>(); }
        else        { cp_wait<0>(); }
        __syncthreads();
        int buf = it & 1;
        #pragma unroll
        for (int k16 = 0; k16 < 2; k16++){
            int kk = k16 << 4;
            uint32_t ah[4][4], bh[4][2];
            #pragma unroll
            for (int mi = 0; mi < 4; mi++){
                int row = wm*64 + mi*16 + (lane & 15);
                ldsm4(ah[mi], aAddr(buf,row,(kk>>3)+(lane>>4)));
            }
            #pragma unroll
            for (int ni = 0; ni < 4; ni++)
                ldsm2t(bh[ni], bAddr(buf, kk + (lane & 15), wn*4 + ni));
            #pragma unroll
            for (int mi = 0; mi < 4; mi++)
                #pragma unroll
                for (int ni = 0; ni < 4; ni++)
                    mma_f16(C[mi][ni], ah[mi], bh[ni]);
        }
        __syncthreads();
    }
    #pragma unroll
    for (int mi = 0; mi < 4; mi++){
        int r0 = oT + wm*64 + mi*16 + (lane >> 2);
        float bi0 = bias[r0]*bsc, bi1 = bias[r0 + 8]*bsc;
        #pragma unroll
        for (int ni = 0; ni < 4; ni++){
            int c0 = nT + wn*32 + ni*8 + (lane & 3)*2;
            size_t o0 = ((size_t)b*NC + r0)*NN + c0;
            *reinterpret_cast<__half2*>(Oh + o0) =
                __floats2half2_rn(C[mi][ni][0]+bi0, C[mi][ni][1]+bi0);
            *reinterpret_cast<__half2*>(Oh + o0 + (size_t)8*NN) =
                __floats2half2_rn(C[mi][ni][2]+bi1, C[mi][ni][3]+bi1);
        }
    }
}

// ---------------- attention: flash-style + online max (log2 domain), fp16 ----------------
// K' = [k*log2e ; q] vs Q' = [q ; pos*log2e]  ->  S is already in log2 units.
__global__ __launch_bounds__(256, 2) void attn_mma_kernel(const float* __restrict__ x,
                                                          float* __restrict__ out)
{
    extern __shared__ uint4 smemraw[];
    const uint32_t sbase = (uint32_t)__cvta_generic_to_shared(smemraw);
    float* smf = reinterpret_cast<float*>(smemraw);
    const int tid = threadIdx.x, lane = tid & 31, warp = tid >> 5;
    const int wm = warp >> 1, wn = warp & 1;
    const int b = blockIdx.z, h = blockIdx.y;
    const int i0 = blockIdx.x * 128;
    const size_t qoff = ((size_t)b*NC + h*ND)*NN;

    auto loadQ = [&](){
        #pragma unroll
        for (int s = 0; s < 8; s++){
            int idx = tid + s*256;
            int r = idx >> 4, u = idx & 15;
            const __half* src = (r < 64)
                ? g_qh + qoff + (size_t)r*NN + i0 + u*8
                : g_ph + ((size_t)h*ND + (r-64))*NN + i0 + u*8;
            cp16(sbase + (uint32_t)(r*16 + (u ^ (r&7)))*16u, src);
        }
    };
    auto loadKV = [&](int jt, int buf){
        int j0 = jt * 64;
        #pragma unroll
        for (int s = 0; s < 4; s++){
            int idx = tid + s*256;
            int r = idx >> 3, u = idx & 7;
            const __half* src = (r < 64)
                ? g_kh + qoff + (size_t)r*NN + j0 + u*8
                : g_qh + qoff + (size_t)(r-64)*NN + j0 + u*8;
            cp16(sbase + (uint32_t)(2048 + buf*1024 + r*8 + (u ^ (r&7)))*16u, src);
        }
        #pragma unroll
        for (int s = 0; s < 2; s++){
            int idx = tid + s*256;
            int r = idx >> 3, u = idx & 7;
            const __half* src = g_vh + qoff + (size_t)r*NN + j0 + u*8;
            cp16(sbase + (uint32_t)(4096 + buf*512 + r*8 + (u ^ (r&7)))*16u, src);
        }
    };

    float Oc[2][8][4];
    #pragma unroll
    for (int a=0;a<2;a++)
        #pragma unroll
        for (int bb=0;bb<8;bb++)
            #pragma unroll
            for (int c=0;c<4;c++) Oc[a][bb][c]=0.f;
    float rs[2][2] = {{0.f,0.f},{0.f,0.f}};
    float mr[2][2] = {{-1e30f,-1e30f},{-1e30f,-1e30f}};

    loadQ(); loadKV(0, 0); cp_commit();

    for (int jt = 0; jt < 16; jt++){
        if (jt < 15){ loadKV(jt+1, (jt+1)&1); cp_commit(); cp_wait<1>(); }
        else        { cp_wait<0>(); }
        __syncthreads();
        int buf = jt & 1;

        float S[2][4][4];
        #pragma unroll
        for (int a=0;a<2;a++)
            #pragma unroll
            for (int bb=0;bb<4;bb++)
                #pragma unroll
                for (int c=0;c<4;c++) S[a][bb][c]=0.f;

        #pragma unroll
        for (int k16 = 0; k16 < 8; k16++){
            uint32_t aH[2][4], bH[4][2];
            int arow = k16*16 + (lane & 7) + ((lane >> 4) << 3);
            #pragma unroll
            for (int mi = 0; mi < 2; mi++){
                int au = wm*4 + mi*2 + ((lane >> 3) & 1);
                ldsm4t(aH[mi], sbase + (uint32_t)(arow*16 + (au ^ (arow&7)))*16u);
            }
            int brow = k16*16 + (lane & 15);
            #pragma unroll
            for (int ni = 0; ni < 4; ni++){
                int bu = wn*4 + ni;
                ldsm2t(bH[ni], sbase + (uint32_t)(2048 + buf*1024 + brow*8 + (bu ^ (brow&7)))*16u);
            }
            #pragma unroll
            for (int mi = 0; mi < 2; mi++)
                #pragma unroll
                for (int ni = 0; ni < 4; ni++)
                    mma_f16(S[mi][ni], aH[mi], bH[ni]);
        }

        // online softmax in log2 domain: P = 2^(S - m)
        #pragma unroll
        for (int mi = 0; mi < 2; mi++){
            float t0 = -1e30f, t1 = -1e30f;
            #pragma unroll
            for (int ni = 0; ni < 4; ni++){
                t0 = fmaxf(t0, fmaxf(S[mi][ni][0], S[mi][ni][1]));
                t1 = fmaxf(t1, fmaxf(S[mi][ni][2], S[mi][ni][3]));
            }
            #pragma unroll
            for (int off = 1; off < 4; off <<= 1){
                t0 = fmaxf(t0, __shfl_xor_sync(0xffffffffu, t0, off));
                t1 = fmaxf(t1, __shfl_xor_sync(0xffffffffu, t1, off));
            }
            float nm0 = fmaxf(mr[mi][0], t0), nm1 = fmaxf(mr[mi][1], t1);
            float sc0 = ex2f(mr[mi][0] - nm0), sc1 = ex2f(mr[mi][1] - nm1);
            mr[mi][0] = nm0; mr[mi][1] = nm1;
            float ps0 = 0.f, ps1 = 0.f;
            #pragma unroll
            for (int ni = 0; ni < 4; ni++){
                S[mi][ni][0] = ex2f(S[mi][ni][0] - nm0);
                S[mi][ni][1] = ex2f(S[mi][ni][1] - nm0);
                S[mi][ni][2] = ex2f(S[mi][ni][2] - nm1);
                S[mi][ni][3] = ex2f(S[mi][ni][3] - nm1);
                ps0 += S[mi][ni][0] + S[mi][ni][1];
                ps1 += S[mi][ni][2] + S[mi][ni][3];
            }
            rs[mi][0] = rs[mi][0]*sc0 + ps0;
            rs[mi][1] = rs[mi][1]*sc1 + ps1;
            #pragma unroll
            for (int nd = 0; nd < 8; nd++){
                Oc[mi][nd][0] *= sc0; Oc[mi][nd][1] *= sc0;
                Oc[mi][nd][2] *= sc1; Oc[mi][nd][3] *= sc1;
            }
        }

        #pragma unroll
        for (int kt = 0; kt < 2; kt++){
            uint32_t pF[2][4];
            #pragma unroll
            for (int mi = 0; mi < 2; mi++){
                pF[mi][0] = packh2(S[mi][2*kt  ][0], S[mi][2*kt  ][1]);
                pF[mi][1] = packh2(S[mi][2*kt  ][2], S[mi][2*kt  ][3]);
                pF[mi][2] = packh2(S[mi][2*kt+1][0], S[mi][2*kt+1][1]);
                pF[mi][3] = packh2(S[mi][2*kt+1][2], S[mi][2*kt+1][3]);
            }
            #pragma unroll
            for (int nd = 0; nd < 8; nd++){
                int vrow = nd*8 + (lane & 7);
                int vu = wn*4 + kt*2 + ((lane >> 3) & 1);
                uint32_t vF[2];
                ldsm2(vF, sbase + (uint32_t)(4096 + buf*512 + vrow*8 + (vu ^ (vrow&7)))*16u);
                #pragma unroll
                for (int mi = 0; mi < 2; mi++)
                    mma_f16(Oc[mi][nd], pF[mi], vF);
            }
        }
        __syncthreads();
    }

    // cross-warp combine (max reconciliation in log2 domain), normalize, +x, store
    float* Os = smf;
    float* rsum_s = smf + 128*65;
    float* mmax_s = rsum_s + 128;
    #pragma unroll
    for (int off = 1; off < 4; off <<= 1)
        #pragma unroll
        for (int mi = 0; mi < 2; mi++){
            rs[mi][0] += __shfl_xor_sync(0xffffffffu, rs[mi][0], off);
            rs[mi][1] += __shfl_xor_sync(0xffffffffu, rs[mi][1], off);
        }
    if (wn == 0){
        #pragma unroll
        for (int mi = 0; mi < 2; mi++){
            int ib = wm*32 + mi*16 + (lane >> 2);
            #pragma unroll
            for (int nd = 0; nd < 8; nd++){
                int dd = nd*8 + (lane & 3)*2;
                Os[ib*65 + dd]       = Oc[mi][nd][0];
                Os[ib*65 + dd + 1]   = Oc[mi][nd][1];
                Os[(ib+8)*65 + dd]   = Oc[mi][nd][2];
                Os[(ib+8)*65 + dd+1] = Oc[mi][nd][3];
            }
            if ((lane & 3) == 0){
                rsum_s[ib]   = rs[mi][0]; rsum_s[ib+8] = rs[mi][1];
                mmax_s[ib]   = mr[mi][0]; mmax_s[ib+8] = mr[mi][1];
            }
        }
    }
    __syncthreads();
    if (wn == 1){
        #pragma unroll
        for (int mi = 0; mi < 2; mi++){
            int ib = wm*32 + mi*16 + (lane >> 2);
            float m0a = mmax_s[ib], m0b = mmax_s[ib+8];
            float Ma = fmaxf(m0a, mr[mi][0]), Mb = fmaxf(m0b, mr[mi][1]);
            float s0a = ex2f(m0a - Ma), s1a = ex2f(mr[mi][0] - Ma);
            float s0b = ex2f(m0b - Mb), s1b = ex2f(mr[mi][1] - Mb);
            #pragma unroll
            for (int nd = 0; nd < 8; nd++){
                int dd = nd*8 + (lane & 3)*2;
                Os[ib*65 + dd]       = Os[ib*65 + dd]      *s0a + Oc[mi][nd][0]*s1a;
                Os[ib*65 + dd + 1]   = Os[ib*65 + dd + 1]  *s0a + Oc[mi][nd][1]*s1a;
                Os[(ib+8)*65 + dd]   = Os[(ib+8)*65 + dd]  *s0b + Oc[mi][nd][2]*s1b;
                Os[(ib+8)*65 + dd+1] = Os[(ib+8)*65 + dd+1]*s0b + Oc[mi][nd][3]*s1b;
            }
            if ((lane & 3) == 0){
                rsum_s[ib]   = rsum_s[ib]  *s0a + rs[mi][0]*s1a;
                rsum_s[ib+8] = rsum_s[ib+8]*s0b + rs[mi][1]*s1b;
            }
        }
    }
    __syncthreads();
    if (tid < 128) rsum_s[tid] = 1.0f / rsum_s[tid];
    __syncthreads();

    const float* xb = x + qoff;
    float* ob = out + qoff;
    #pragma unroll
    for (int s = 0; s < 32; s++){
        int idx = tid + s*256;
        int dd = idx >> 7, iL = idx & 127;
        ob[(size_t)dd*NN + i0 + iL] =
            Os[iL*65 + dd] * rsum_s[iL] + xb[(size_t)dd*NN + i0 + iL];
    }
}

extern "C" void kernel_launch(void* const* d_in, const int* in_sizes, int n_in,
                              void* d_out, int out_size) {
    (void)in_sizes; (void)n_in; (void)out_size;
    const float* x     = (const float*)d_in[0];
    const float* Wq    = (const float*)d_in[1];
    const float* bq    = (const float*)d_in[2];
    const float* Wk    = (const float*)d_in[3];
    const float* bk    = (const float*)d_in[4];
    const float* Wv    = (const float*)d_in[5];
    const float* bv    = (const float*)d_in[6];
    const float* rel_h = (const float*)d_in[7];
    const float* rel_w = (const float*)d_in[8];
    // d_in[9]/d_in[10] (reg_qk/reg_v) provably dead (sliced away by out[:, :head]).
    float* out = (float*)d_out;

    cudaFuncSetAttribute(qkv_mma_kernel,
        cudaFuncAttributeMaxDynamicSharedMemorySize, 32768);
    cudaFuncSetAttribute(attn_mma_kernel,
        cudaFuncAttributeMaxDynamicSharedMemorySize, 81920);

    cvt_all_kernel<<<(X4 + 3*W4 + 255)/256, 256>>>(x, Wq, Wk, Wv);
    pos_cvt_kernel<<<2048, 256>>>(rel_h, rel_w);
    qkv_mma_kernel<<<dim3(NN/128, NC/128, 3*NB), 256, 32768>>>(bq, bk, bv);
    attn_mma_kernel<<<dim3(NN/128, NH, NB), 256, 81920>>>(x, out);
}